// round 1
// baseline (speedup 1.0000x reference)
#include <cuda_runtime.h>
#include <math.h>

#define NPIX 50176
#define CF   4224
#define NS   128
#define DH   1024

// ---------------- scratch (static device memory only; no allocation) -------
__device__ int   g_hist[NS];
__device__ int   g_cls[NS * 3];
__device__ int   g_off[NS + 1];
__device__ int   g_cur[NS];
__device__ int   g_perm[NPIX];
__device__ int   g_lab[NS];
__device__ float g_feat[NS * CF];
__device__ float g_G[NS * NS];
__device__ float g_h1[NS * DH];
__device__ float g_h2[NS * DH];
__device__ float g_h3[NS * 32];

// ---------------- K0: zero the accumulators used with atomics --------------
__global__ void k_zero() {
    int i = blockIdx.x * blockDim.x + threadIdx.x;
    if (i < NS * DH) { g_h1[i] = 0.f; g_h2[i] = 0.f; }
    if (i < NS * NS) g_G[i] = 0.f;
    if (i < NS * 3)  g_cls[i] = 0;
    if (i < NS)      { g_hist[i] = 0; g_cur[i] = 0; }
}

// ---------------- K1: per-segment counts + class counts --------------------
__global__ void k_hist(const int* __restrict__ sp, const int* __restrict__ y) {
    __shared__ int sh[NS];
    __shared__ int sc[NS * 3];
    for (int i = threadIdx.x; i < NS; i += blockDim.x) sh[i] = 0;
    for (int i = threadIdx.x; i < NS * 3; i += blockDim.x) sc[i] = 0;
    __syncthreads();
    for (int i = blockIdx.x * blockDim.x + threadIdx.x; i < NPIX;
         i += gridDim.x * blockDim.x) {
        int s = sp[i];
        atomicAdd(&sh[s], 1);
        atomicAdd(&sc[s * 3 + y[i]], 1);
    }
    __syncthreads();
    for (int i = threadIdx.x; i < NS; i += blockDim.x)
        if (sh[i]) atomicAdd(&g_hist[i], sh[i]);
    for (int i = threadIdx.x; i < NS * 3; i += blockDim.x)
        if (sc[i]) atomicAdd(&g_cls[i], sc[i]);
}

// ---------------- K2: offsets prefix-sum + exact integer label logic -------
__global__ void k_meta() {
    int s = threadIdx.x;  // 128 threads
    if (s == 0) {
        int acc = 0;
        for (int i = 0; i < NS; i++) { g_off[i] = acc; acc += g_hist[i]; }
        g_off[NS] = acc;
    }
    int c0 = g_cls[s * 3 + 0];
    int c1 = g_cls[s * 3 + 1];
    int c2 = g_cls[s * 3 + 2];
    // jnp.argmax: first index of max
    int lab = (c1 > c0) ? ((c2 > c1) ? 2 : 1) : ((c2 > c0) ? 2 : 0);
    if (lab == 0) {
        int cnt = g_hist[s];
        // twos_c > floor(counts*0.5)  (counts are exact small ints in fp32)
        lab = (c2 > (cnt >> 1)) ? 2 : ((c1 >= 1) ? 1 : 0);
    }
    g_lab[s] = lab;
}

// ---------------- K3: scatter pixel indices into segment-sorted order ------
__global__ void k_scatter(const int* __restrict__ sp) {
    int i = blockIdx.x * blockDim.x + threadIdx.x;
    if (i < NPIX) {
        int s = sp[i];
        int p = atomicAdd(&g_cur[s], 1);
        g_perm[g_off[s] + p] = i;
    }
}

// ---------------- K4: segment mean features (streams the 847 MB) -----------
// grid = (33 col-tiles of 128, 128 segments), block = 256 (32 quads x 8 rows)
__global__ void k_segsum(const float* __restrict__ pix) {
    int ct = blockIdx.x;
    int s  = blockIdx.y;
    int tx = threadIdx.x & 31;
    int ty = threadIdx.x >> 5;
    int beg = g_off[s], end = g_off[s + 1];
    const float4* __restrict__ p4 = (const float4*)pix;
    const int rowq = CF / 4;             // 1056 float4 per row
    int colq = ct * 32 + tx;

    float4 a0 = make_float4(0.f, 0.f, 0.f, 0.f);
    float4 a1 = make_float4(0.f, 0.f, 0.f, 0.f);
    int r = beg + ty;
    // unroll x2 for memory-level parallelism
    for (; r + 8 < end; r += 16) {
        int i0 = g_perm[r];
        int i1 = g_perm[r + 8];
        float4 v0 = __ldg(p4 + (size_t)i0 * rowq + colq);
        float4 v1 = __ldg(p4 + (size_t)i1 * rowq + colq);
        a0.x += v0.x; a0.y += v0.y; a0.z += v0.z; a0.w += v0.w;
        a1.x += v1.x; a1.y += v1.y; a1.z += v1.z; a1.w += v1.w;
    }
    if (r < end) {
        int i0 = g_perm[r];
        float4 v0 = __ldg(p4 + (size_t)i0 * rowq + colq);
        a0.x += v0.x; a0.y += v0.y; a0.z += v0.z; a0.w += v0.w;
    }
    a0.x += a1.x; a0.y += a1.y; a0.z += a1.z; a0.w += a1.w;

    __shared__ float4 red[8][32];
    red[ty][tx] = a0;
    __syncthreads();
    if (ty == 0) {
        float4 t = red[0][tx];
        #pragma unroll
        for (int w = 1; w < 8; w++) {
            t.x += red[w][tx].x; t.y += red[w][tx].y;
            t.z += red[w][tx].z; t.w += red[w][tx].w;
        }
        float c = (float)max(end - beg, 1);
        t.x /= c; t.y /= c; t.z /= c; t.w /= c;
        *(float4*)&g_feat[s * CF + colq * 4] = t;
    }
}

// ---------------- K5: Gram matrix G = feat @ feat^T (split-K, 66 blocks) ---
__global__ void k_gram() {
    __shared__ float As[64][129];  // [k][i], pad 129 -> conflict-free staging
    int kc  = blockIdx.x;          // 66 chunks of 64 along K
    int tid = threadIdx.x;
    {
        int k  = tid & 63;
        int io = tid >> 6;
        #pragma unroll 8
        for (int p = 0; p < 32; p++) {
            int i = p * 4 + io;
            As[k][i] = g_feat[i * CF + kc * 64 + k];
        }
    }
    __syncthreads();
    int tx = tid & 15, ty = tid >> 4;
    float acc[8][8];
    #pragma unroll
    for (int m = 0; m < 8; m++)
        #pragma unroll
        for (int n = 0; n < 8; n++) acc[m][n] = 0.f;

    for (int kk = 0; kk < 64; kk++) {
        float a[8], b[8];
        #pragma unroll
        for (int m = 0; m < 8; m++) a[m] = As[kk][ty * 8 + m];
        #pragma unroll
        for (int n = 0; n < 8; n++) b[n] = As[kk][tx * 8 + n];
        #pragma unroll
        for (int m = 0; m < 8; m++)
            #pragma unroll
            for (int n = 0; n < 8; n++) acc[m][n] += a[m] * b[n];
    }
    #pragma unroll
    for (int m = 0; m < 8; m++)
        #pragma unroll
        for (int n = 0; n < 8; n++)
            atomicAdd(&g_G[(ty * 8 + m) * NS + tx * 8 + n], acc[m][n]);
}

// ---------------- K6: affinity-based label propagation + lab output --------
__global__ void k_labels(float* __restrict__ out_lab) {
    __shared__ float nrm[NS];
    __shared__ int   labsh[NS];
    int i = threadIdx.x;  // 128 threads
    labsh[i] = g_lab[i];
    nrm[i] = rsqrtf(g_G[i * NS + i]);
    __syncthreads();
    float maxv = -__int_as_float(0x7f800000);  // -inf
    int best = 0;
    float ni = nrm[i];
    for (int j = 0; j < NS; j++) {
        if (labsh[j] != 0) {
            float a = g_G[i * NS + j] * ni * nrm[j];
            if (a > maxv) { maxv = a; best = j; }  // strict > => first max
        }
    }
    int lab = labsh[i];
    if (lab == 0 && maxv > 0.8f) lab = labsh[best];
    out_lab[i] = (float)lab;
}

// ---------------- K7/K8: MLP GEMMs (split-K tiled fp32, atomic combine) ----
// L==1: g_h1 = g_feat @ w1        (K=4224, kchunk=528)
// L==2: g_h2 = relu(g_h1+b1) @ w2 (K=1024, kchunk=128)
template <int L>
__global__ void k_mlp_gemm(const float* __restrict__ B,
                           const float* __restrict__ bias) {
    const float* __restrict__ A = (L == 1) ? g_feat : g_h1;
    float* C = (L == 1) ? g_h1 : g_h2;
    const int K      = (L == 1) ? CF : DH;
    const int kchunk = (L == 1) ? 528 : 128;
    const int N = DH;

    __shared__ float As[16][132];  // [k][row]
    __shared__ float Bs[16][68];   // [k][col]
    int tid = threadIdx.x;
    int tx = tid & 15, ty = tid >> 4;
    int ntile = blockIdx.x;
    int k0 = blockIdx.y * kchunk;

    float acc[8][4];
    #pragma unroll
    for (int m = 0; m < 8; m++)
        #pragma unroll
        for (int n = 0; n < 4; n++) acc[m][n] = 0.f;

    for (int kt = 0; kt < kchunk; kt += 16) {
        // stage A: 128 rows x 16 k, transposed into As[k][row]
        #pragma unroll
        for (int p = 0; p < 8; p++) {
            int r = ty + p * 16;
            int kg = k0 + kt + tx;
            float v = A[r * K + kg];
            if (L == 2) v = fmaxf(v + bias[kg], 0.f);
            As[tx][r] = v;
        }
        // stage B: 16 k x 64 cols
        #pragma unroll
        for (int p = 0; p < 4; p++) {
            int k = p * 4 + (tid >> 6);
            int n = tid & 63;
            Bs[k][n] = B[(k0 + kt + k) * N + ntile * 64 + n];
        }
        __syncthreads();
        #pragma unroll
        for (int kk = 0; kk < 16; kk++) {
            float a[8], b[4];
            #pragma unroll
            for (int m = 0; m < 8; m++) a[m] = As[kk][ty * 8 + m];
            #pragma unroll
            for (int n = 0; n < 4; n++) b[n] = Bs[kk][tx * 4 + n];
            #pragma unroll
            for (int m = 0; m < 8; m++)
                #pragma unroll
                for (int n = 0; n < 4; n++) acc[m][n] += a[m] * b[n];
        }
        __syncthreads();
    }
    #pragma unroll
    for (int m = 0; m < 8; m++) {
        int r = ty * 8 + m;
        #pragma unroll
        for (int n = 0; n < 4; n++)
            atomicAdd(&C[r * N + ntile * 64 + tx * 4 + n], acc[m][n]);
    }
}

// ---------------- K9: h3 = relu(h2+b2) @ w3  (128x32, K=1024) --------------
__global__ void k_gemm3(const float* __restrict__ b2,
                        const float* __restrict__ w3) {
    int idx = blockIdx.x * blockDim.x + threadIdx.x;  // 4096
    int i = idx >> 5, j = idx & 31;
    const float* __restrict__ h2r = g_h2 + i * DH;
    float acc = 0.f;
    #pragma unroll 8
    for (int k = 0; k < DH; k++)
        acc += fmaxf(h2r[k] + b2[k], 0.f) * w3[k * 32 + j];
    g_h3[idx] = acc;
}

// ---------------- K10: classifier head + softmax -> probs ------------------
__global__ void k_head(const float* __restrict__ b3,
                       const float* __restrict__ wc,
                       const float* __restrict__ bc,
                       float* __restrict__ out_probs) {
    int i = threadIdx.x;  // 128
    float l0 = bc[0], l1 = bc[1];
    #pragma unroll
    for (int k = 0; k < 32; k++) {
        float h = fmaxf(g_h3[i * 32 + k] + b3[k], 0.f);
        l0 += h * wc[k * 2 + 0];
        l1 += h * wc[k * 2 + 1];
    }
    float m = fmaxf(l0, l1);
    float e0 = expf(l0 - m), e1 = expf(l1 - m);
    float s = e0 + e1;
    out_probs[i * 2 + 0] = e0 / s;
    out_probs[i * 2 + 1] = e1 / s;
}

// ---------------- launch ----------------------------------------------------
extern "C" void kernel_launch(void* const* d_in, const int* in_sizes, int n_in,
                              void* d_out, int out_size) {
    const float* pixfeat = (const float*)d_in[0];
    const float* w1 = (const float*)d_in[1];
    const float* b1 = (const float*)d_in[2];
    const float* w2 = (const float*)d_in[3];
    const float* b2 = (const float*)d_in[4];
    const float* w3 = (const float*)d_in[5];
    const float* b3 = (const float*)d_in[6];
    const float* wc = (const float*)d_in[7];
    const float* bc = (const float*)d_in[8];
    const int*   sp = (const int*)d_in[9];
    const int*   yy = (const int*)d_in[10];
    float* out = (float*)d_out;  // [0,256): probs row-major, [256,384): lab

    k_zero<<<512, 256>>>();
    k_hist<<<128, 256>>>(sp, yy);
    k_meta<<<1, 128>>>();
    k_scatter<<<NPIX / 256, 256>>>(sp);
    k_segsum<<<dim3(33, 128), 256>>>(pixfeat);
    k_gram<<<66, 256>>>();
    k_labels<<<1, 128>>>(out + 256);
    k_mlp_gemm<1><<<dim3(16, 8), 256>>>(w1, nullptr);
    k_mlp_gemm<2><<<dim3(16, 8), 256>>>(w2, b1);
    k_gemm3<<<32, 128>>>(b2, w3);
    k_head<<<1, 128>>>(b3, wc, bc, out);
}

// round 2
// speedup vs baseline: 1.0672x; 1.0672x over previous
#include <cuda_runtime.h>
#include <math.h>

#define NPIX 50176
#define CF   4224
#define NS   128
#define DH   1024
#define PPB  392          // NPIX / 128 pixels per histogram/scatter block
#define SEGCAP 768        // smem index-staging cap (mean 392, sd ~20 -> 12+ sigma)

// ---------------- scratch (static device memory only) ----------------------
__device__ int   g_hist[NS];
__device__ int   g_cls[NS * 3];
__device__ int   g_off[NS + 1];
__device__ int   g_bh[NS * NS];     // per-block per-segment counts
__device__ int   g_bbase[NS * NS];  // per-block per-segment write bases
__device__ int   g_perm[NPIX];
__device__ int   g_lab[NS];
__device__ float g_feat[NS * CF];
__device__ float g_G[NS * NS];
__device__ float g_h1[NS * DH];
__device__ float g_h2[NS * DH];
__device__ float g_h3[NS * 32];

// ---------------- K0: zero atomic accumulators ------------------------------
__global__ void k_zero() {
    int i = blockIdx.x * blockDim.x + threadIdx.x;
    if (i < NS * DH) { g_h1[i] = 0.f; g_h2[i] = 0.f; }
    if (i < NS * NS) g_G[i] = 0.f;
    if (i < NS * 3)  g_cls[i] = 0;
}

// ---------------- K1: per-block segment histograms + class counts ----------
__global__ void k_hist(const int* __restrict__ sp, const int* __restrict__ y) {
    __shared__ int sh[NS];
    __shared__ int sc[NS * 3];
    for (int i = threadIdx.x; i < NS; i += 256) sh[i] = 0;
    for (int i = threadIdx.x; i < NS * 3; i += 256) sc[i] = 0;
    __syncthreads();
    int b = blockIdx.x;
    int base = b * PPB;
    for (int t = threadIdx.x; t < PPB; t += 256) {
        int i = base + t;
        int s = sp[i];
        atomicAdd(&sh[s], 1);
        atomicAdd(&sc[s * 3 + y[i]], 1);
    }
    __syncthreads();
    for (int i = threadIdx.x; i < NS; i += 256) g_bh[b * NS + i] = sh[i];
    for (int i = threadIdx.x; i < NS * 3; i += 256)
        if (sc[i]) atomicAdd(&g_cls[i], sc[i]);
}

// ---------------- K2: offsets, per-block bases, exact label logic ----------
__global__ void k_meta() {
    int s = threadIdx.x;  // 128 threads
    __shared__ int tot[NS];
    int acc = 0;
    #pragma unroll 4
    for (int b = 0; b < NS; b++) acc += g_bh[b * NS + s];
    tot[s] = acc;
    g_hist[s] = acc;
    __syncthreads();
    if (s == 0) {
        int a = 0;
        for (int i = 0; i < NS; i++) { g_off[i] = a; a += tot[i]; }
        g_off[NS] = a;
    }
    __syncthreads();
    int base = g_off[s];
    #pragma unroll 4
    for (int b = 0; b < NS; b++) {
        g_bbase[b * NS + s] = base;
        base += g_bh[b * NS + s];
    }
    int c0 = g_cls[s * 3 + 0];
    int c1 = g_cls[s * 3 + 1];
    int c2 = g_cls[s * 3 + 2];
    int lab = (c1 > c0) ? ((c2 > c1) ? 2 : 1) : ((c2 > c0) ? 2 : 0);
    if (lab == 0) {
        int cnt = g_hist[s];
        lab = (c2 > (cnt >> 1)) ? 2 : ((c1 >= 1) ? 1 : 0);
    }
    g_lab[s] = lab;
}

// ---------------- K3: scatter via smem atomics against precomputed bases ---
__global__ void k_scatter(const int* __restrict__ sp) {
    __shared__ int cur[NS];
    int b = blockIdx.x;
    for (int i = threadIdx.x; i < NS; i += 256) cur[i] = g_bbase[b * NS + i];
    __syncthreads();
    int base = b * PPB;
    for (int t = threadIdx.x; t < PPB; t += 256) {
        int i = base + t;
        int s = sp[i];
        int p = atomicAdd(&cur[s], 1);
        g_perm[p] = i;
    }
}

// ---------------- K4: segment mean features (streams the 847 MB) -----------
// grid = (33 col-tiles of 128 floats, 128 segments), block = 256 (8x32)
// Perm indices staged in smem -> address path is LDS (29 cyc); data loads are
// 4 independent LDG.128 per thread -> deep MLP, DRAM-latency covered.
__global__ void k_segsum(const float* __restrict__ pix) {
    int ct = blockIdx.x;
    int s  = blockIdx.y;
    int tx = threadIdx.x & 31;
    int ty = threadIdx.x >> 5;
    int beg = g_off[s], end = g_off[s + 1];
    int n = end - beg;

    __shared__ int sidx[SEGCAP];
    int cap = n < SEGCAP ? n : SEGCAP;
    for (int i = threadIdx.x; i < cap; i += 256) sidx[i] = g_perm[beg + i];
    __syncthreads();

    const float4* __restrict__ p4 = (const float4*)pix;
    const int rowq = CF / 4;  // 1056
    int colq = ct * 32 + tx;

    float4 a0 = make_float4(0.f, 0.f, 0.f, 0.f);
    float4 a1 = make_float4(0.f, 0.f, 0.f, 0.f);
    float4 a2 = make_float4(0.f, 0.f, 0.f, 0.f);
    float4 a3 = make_float4(0.f, 0.f, 0.f, 0.f);

    int r = ty;
    for (; r + 24 < cap; r += 32) {
        int i0 = sidx[r];
        int i1 = sidx[r + 8];
        int i2 = sidx[r + 16];
        int i3 = sidx[r + 24];
        float4 v0 = __ldg(p4 + (size_t)i0 * rowq + colq);
        float4 v1 = __ldg(p4 + (size_t)i1 * rowq + colq);
        float4 v2 = __ldg(p4 + (size_t)i2 * rowq + colq);
        float4 v3 = __ldg(p4 + (size_t)i3 * rowq + colq);
        a0.x += v0.x; a0.y += v0.y; a0.z += v0.z; a0.w += v0.w;
        a1.x += v1.x; a1.y += v1.y; a1.z += v1.z; a1.w += v1.w;
        a2.x += v2.x; a2.y += v2.y; a2.z += v2.z; a2.w += v2.w;
        a3.x += v3.x; a3.y += v3.y; a3.z += v3.z; a3.w += v3.w;
    }
    for (; r < cap; r += 8) {
        int i0 = sidx[r];
        float4 v0 = __ldg(p4 + (size_t)i0 * rowq + colq);
        a0.x += v0.x; a0.y += v0.y; a0.z += v0.z; a0.w += v0.w;
    }
    // fallback for (vanishingly unlikely) segments larger than SEGCAP
    for (int r2 = SEGCAP + ty; r2 < n; r2 += 8) {
        int i0 = g_perm[beg + r2];
        float4 v0 = __ldg(p4 + (size_t)i0 * rowq + colq);
        a0.x += v0.x; a0.y += v0.y; a0.z += v0.z; a0.w += v0.w;
    }
    a0.x += a1.x + a2.x + a3.x;
    a0.y += a1.y + a2.y + a3.y;
    a0.z += a1.z + a2.z + a3.z;
    a0.w += a1.w + a2.w + a3.w;

    __shared__ float4 red[8][32];
    red[ty][tx] = a0;
    __syncthreads();
    if (ty == 0) {
        float4 t = red[0][tx];
        #pragma unroll
        for (int w = 1; w < 8; w++) {
            t.x += red[w][tx].x; t.y += red[w][tx].y;
            t.z += red[w][tx].z; t.w += red[w][tx].w;
        }
        float c = (float)max(n, 1);
        t.x /= c; t.y /= c; t.z /= c; t.w /= c;
        *(float4*)&g_feat[s * CF + colq * 4] = t;
    }
}

// ---------------- K5: Gram matrix G = feat @ feat^T (split-K, 66 blocks) ---
__global__ void k_gram() {
    __shared__ float As[64][129];
    int kc  = blockIdx.x;
    int tid = threadIdx.x;
    {
        int k  = tid & 63;
        int io = tid >> 6;
        #pragma unroll 8
        for (int p = 0; p < 32; p++) {
            int i = p * 4 + io;
            As[k][i] = g_feat[i * CF + kc * 64 + k];
        }
    }
    __syncthreads();
    int tx = tid & 15, ty = tid >> 4;
    float acc[8][8];
    #pragma unroll
    for (int m = 0; m < 8; m++)
        #pragma unroll
        for (int n = 0; n < 8; n++) acc[m][n] = 0.f;

    for (int kk = 0; kk < 64; kk++) {
        float a[8], b[8];
        #pragma unroll
        for (int m = 0; m < 8; m++) a[m] = As[kk][ty * 8 + m];
        #pragma unroll
        for (int n = 0; n < 8; n++) b[n] = As[kk][tx * 8 + n];
        #pragma unroll
        for (int m = 0; m < 8; m++)
            #pragma unroll
            for (int n = 0; n < 8; n++) acc[m][n] += a[m] * b[n];
    }
    #pragma unroll
    for (int m = 0; m < 8; m++)
        #pragma unroll
        for (int n = 0; n < 8; n++)
            atomicAdd(&g_G[(ty * 8 + m) * NS + tx * 8 + n], acc[m][n]);
}

// ---------------- K6: affinity-based label propagation ----------------------
__global__ void k_labels(float* __restrict__ out_lab) {
    __shared__ float nrm[NS];
    __shared__ int   labsh[NS];
    int i = threadIdx.x;
    labsh[i] = g_lab[i];
    nrm[i] = rsqrtf(g_G[i * NS + i]);
    __syncthreads();
    float maxv = -__int_as_float(0x7f800000);
    int best = 0;
    float ni = nrm[i];
    for (int j = 0; j < NS; j++) {
        if (labsh[j] != 0) {
            float a = g_G[i * NS + j] * ni * nrm[j];
            if (a > maxv) { maxv = a; best = j; }
        }
    }
    int lab = labsh[i];
    if (lab == 0 && maxv > 0.8f) lab = labsh[best];
    out_lab[i] = (float)lab;
}

// ---------------- K7/K8: MLP GEMMs (split-K tiled fp32, atomic combine) ----
// L==1: g_h1 = g_feat @ w1        (K=4224, 33 chunks of 128)
// L==2: g_h2 = relu(g_h1+b1) @ w2 (K=1024,  8 chunks of 128)
template <int L>
__global__ void k_mlp_gemm(const float* __restrict__ B,
                           const float* __restrict__ bias) {
    const float* __restrict__ A = (L == 1) ? g_feat : g_h1;
    float* C = (L == 1) ? g_h1 : g_h2;
    const int K = (L == 1) ? CF : DH;
    const int N = DH;
    const int KCHUNK = 128;

    __shared__ float As[16][132];
    __shared__ float Bs[16][68];
    int tid = threadIdx.x;
    int tx = tid & 15, ty = tid >> 4;
    int ntile = blockIdx.x;
    int k0 = blockIdx.y * KCHUNK;

    float acc[8][4];
    #pragma unroll
    for (int m = 0; m < 8; m++)
        #pragma unroll
        for (int n = 0; n < 4; n++) acc[m][n] = 0.f;

    for (int kt = 0; kt < KCHUNK; kt += 16) {
        #pragma unroll
        for (int p = 0; p < 8; p++) {
            int r = ty + p * 16;
            int kg = k0 + kt + tx;
            float v = A[r * K + kg];
            if (L == 2) v = fmaxf(v + bias[kg], 0.f);
            As[tx][r] = v;
        }
        #pragma unroll
        for (int p = 0; p < 4; p++) {
            int k = p * 4 + (tid >> 6);
            int n = tid & 63;
            Bs[k][n] = B[(k0 + kt + k) * N + ntile * 64 + n];
        }
        __syncthreads();
        #pragma unroll
        for (int kk = 0; kk < 16; kk++) {
            float a[8], b[4];
            #pragma unroll
            for (int m = 0; m < 8; m++) a[m] = As[kk][ty * 8 + m];
            #pragma unroll
            for (int n = 0; n < 4; n++) b[n] = Bs[kk][tx * 4 + n];
            #pragma unroll
            for (int m = 0; m < 8; m++)
                #pragma unroll
                for (int n = 0; n < 4; n++) acc[m][n] += a[m] * b[n];
        }
        __syncthreads();
    }
    #pragma unroll
    for (int m = 0; m < 8; m++) {
        int r = ty * 8 + m;
        #pragma unroll
        for (int n = 0; n < 4; n++)
            atomicAdd(&C[r * N + ntile * 64 + tx * 4 + n], acc[m][n]);
    }
}

// ---------------- K9: h3 = relu(h2+b2) @ w3  (128x32, K=1024) --------------
__global__ void k_gemm3(const float* __restrict__ b2,
                        const float* __restrict__ w3) {
    int idx = blockIdx.x * blockDim.x + threadIdx.x;
    int i = idx >> 5, j = idx & 31;
    const float* __restrict__ h2r = g_h2 + i * DH;
    float acc = 0.f;
    #pragma unroll 8
    for (int k = 0; k < DH; k++)
        acc += fmaxf(h2r[k] + b2[k], 0.f) * w3[k * 32 + j];
    g_h3[idx] = acc;
}

// ---------------- K10: classifier head + softmax ----------------------------
__global__ void k_head(const float* __restrict__ b3,
                       const float* __restrict__ wc,
                       const float* __restrict__ bc,
                       float* __restrict__ out_probs) {
    int i = threadIdx.x;
    float l0 = bc[0], l1 = bc[1];
    #pragma unroll
    for (int k = 0; k < 32; k++) {
        float h = fmaxf(g_h3[i * 32 + k] + b3[k], 0.f);
        l0 += h * wc[k * 2 + 0];
        l1 += h * wc[k * 2 + 1];
    }
    float m = fmaxf(l0, l1);
    float e0 = expf(l0 - m), e1 = expf(l1 - m);
    float s = e0 + e1;
    out_probs[i * 2 + 0] = e0 / s;
    out_probs[i * 2 + 1] = e1 / s;
}

// ---------------- launch ----------------------------------------------------
extern "C" void kernel_launch(void* const* d_in, const int* in_sizes, int n_in,
                              void* d_out, int out_size) {
    const float* pixfeat = (const float*)d_in[0];
    const float* w1 = (const float*)d_in[1];
    const float* b1 = (const float*)d_in[2];
    const float* w2 = (const float*)d_in[3];
    const float* b2 = (const float*)d_in[4];
    const float* w3 = (const float*)d_in[5];
    const float* b3 = (const float*)d_in[6];
    const float* wc = (const float*)d_in[7];
    const float* bc = (const float*)d_in[8];
    const int*   sp = (const int*)d_in[9];
    const int*   yy = (const int*)d_in[10];
    float* out = (float*)d_out;  // [0,256): probs, [256,384): lab

    k_zero<<<512, 256>>>();
    k_hist<<<128, 256>>>(sp, yy);
    k_meta<<<1, 128>>>();
    k_scatter<<<128, 256>>>(sp);
    k_segsum<<<dim3(33, 128), 256>>>(pixfeat);
    k_gram<<<66, 256>>>();
    k_labels<<<1, 128>>>(out + 256);
    k_mlp_gemm<1><<<dim3(16, 33), 256>>>(w1, nullptr);
    k_mlp_gemm<2><<<dim3(16, 8), 256>>>(w2, b1);
    k_gemm3<<<32, 128>>>(b2, w3);
    k_head<<<1, 128>>>(b3, wc, bc, out);
}